// round 1
// baseline (speedup 1.0000x reference)
#include <cuda_runtime.h>
#include <cstdint>

#define D          256
#define NCODES     1024
#define BM         64
#define BN         128
#define KC         64
#define XS_STRIDE  66     // pad: keeps 8B alignment for LDS.64, 2-way STS conflict only
#define ES_STRIDE  129    // odd pad: conflict-free transposed store + scalar load

#define SMEM_WORDS (D * XS_STRIDE + KC * ES_STRIDE)
#define SMEM_BYTES (SMEM_WORDS * 4 + BM * 4)

__device__ float g_e_half[NCODES];

// Precompute 0.5 * ||e_n||^2
__global__ void e_half_kernel(const float* __restrict__ E) {
    int n = blockIdx.x * blockDim.x + threadIdx.x;
    if (n >= NCODES) return;
    const float4* row = reinterpret_cast<const float4*>(E + (size_t)n * D);
    float s = 0.f;
#pragma unroll
    for (int i = 0; i < D / 4; i++) {
        float4 v = row[i];
        s += v.x * v.x + v.y * v.y + v.z * v.z + v.w * v.w;
    }
    g_e_half[n] = 0.5f * s;
}

#define FMA2(c, a, b) asm("fma.rn.f32x2 %0, %1, %2, %0;" : "+l"(c) : "l"(a), "l"(b))
#define DUP32(d, s)   asm("mov.b64 %0, {%1, %1};" : "=l"(d) : "r"(s))

__global__ __launch_bounds__(256, 2)
void vq_kernel(const float* __restrict__ X,
               const float* __restrict__ E,
               float* __restrict__ out) {
    extern __shared__ float smem[];
    float* xs = smem;                      // [D][XS_STRIDE]   (k-major, rows contiguous)
    float* es = smem + D * XS_STRIDE;      // [KC][ES_STRIDE]  (k-major, codes contiguous)
    int*   sIdx = (int*)(es + KC * ES_STRIDE);

    const int tx  = threadIdx.x;           // 0..31  (lane)
    const int ty  = threadIdx.y;           // 0..7   (warp)
    const int tid = ty * 32 + tx;
    const int row0 = blockIdx.x * BM;

    // ---- load x tile, transposed: xs[k][row]. Coalesced along k. ----
    for (int idx = tid; idx < BM * D; idx += 256) {
        int row = idx >> 8;                 // idx / D
        int k   = idx & (D - 1);
        xs[k * XS_STRIDE + row] = X[(size_t)(row0 + row) * D + k];
    }

    // per-thread running best for its 8 rows (rows ty*8 .. ty*8+7)
    float bs[8];
    int   bi[8];
#pragma unroll
    for (int i = 0; i < 8; i++) { bs[i] = -3.4e38f; bi[i] = 0; }

    for (int n0 = 0; n0 < NCODES; n0 += BN) {
        unsigned long long acc[16];         // [rowpair i=0..3][colgroup j=0..3]
#pragma unroll
        for (int i = 0; i < 16; i++) acc[i] = 0ull;

        for (int kc = 0; kc < D; kc += KC) {
            __syncthreads();                // protect es from previous chunk's readers
            // ---- load E chunk, transposed: es[kk][n]. Coalesced along k. ----
            for (int idx = tid; idx < BN * KC; idx += 256) {
                int n  = idx >> 6;
                int kk = idx & (KC - 1);
                es[kk * ES_STRIDE + n] = E[(size_t)(n0 + n) * D + kc + kk];
            }
            __syncthreads();

#pragma unroll 8
            for (int kk = 0; kk < KC; kk++) {
                const float* xp = xs + (kc + kk) * XS_STRIDE + ty * 8;
                unsigned long long a0 = *(const unsigned long long*)(xp + 0);
                unsigned long long a1 = *(const unsigned long long*)(xp + 2);
                unsigned long long a2 = *(const unsigned long long*)(xp + 4);
                unsigned long long a3 = *(const unsigned long long*)(xp + 6);

                const float* ep = es + kk * ES_STRIDE + tx;
                unsigned b0 = __float_as_uint(ep[0]);
                unsigned b1 = __float_as_uint(ep[32]);
                unsigned b2 = __float_as_uint(ep[64]);
                unsigned b3 = __float_as_uint(ep[96]);
                unsigned long long B0, B1, B2, B3;
                DUP32(B0, b0); DUP32(B1, b1); DUP32(B2, b2); DUP32(B3, b3);

                FMA2(acc[0],  a0, B0); FMA2(acc[1],  a0, B1);
                FMA2(acc[2],  a0, B2); FMA2(acc[3],  a0, B3);
                FMA2(acc[4],  a1, B0); FMA2(acc[5],  a1, B1);
                FMA2(acc[6],  a1, B2); FMA2(acc[7],  a1, B3);
                FMA2(acc[8],  a2, B0); FMA2(acc[9],  a2, B1);
                FMA2(acc[10], a2, B2); FMA2(acc[11], a2, B3);
                FMA2(acc[12], a3, B0); FMA2(acc[13], a3, B1);
                FMA2(acc[14], a3, B2); FMA2(acc[15], a3, B3);
            }
        }

        // ---- epilogue for this code tile: score = xe - 0.5*||e||^2, update best ----
        float eh[4];
#pragma unroll
        for (int j = 0; j < 4; j++) eh[j] = g_e_half[n0 + tx + 32 * j];

#pragma unroll
        for (int i = 0; i < 4; i++) {
#pragma unroll
            for (int j = 0; j < 4; j++) {
                unsigned lo_u, hi_u;
                asm("mov.b64 {%0, %1}, %2;" : "=r"(lo_u), "=r"(hi_u) : "l"(acc[i * 4 + j]));
                float slo = __uint_as_float(lo_u) - eh[j];
                float shi = __uint_as_float(hi_u) - eh[j];
                int n = n0 + tx + 32 * j;
                // strict > keeps the earliest (smallest) index among exact ties,
                // since we visit codes in ascending n order per thread.
                if (slo > bs[2 * i])     { bs[2 * i]     = slo; bi[2 * i]     = n; }
                if (shi > bs[2 * i + 1]) { bs[2 * i + 1] = shi; bi[2 * i + 1] = n; }
            }
        }
    }

    // ---- warp-level argmax reduction across the 32 lanes holding each row ----
#pragma unroll
    for (int i = 0; i < 8; i++) {
        float s  = bs[i];
        int   ix = bi[i];
#pragma unroll
        for (int off = 16; off > 0; off >>= 1) {
            float so = __shfl_down_sync(0xffffffffu, s, off);
            int   io = __shfl_down_sync(0xffffffffu, ix, off);
            if (so > s || (so == s && io < ix)) { s = so; ix = io; }
        }
        if (tx == 0) sIdx[ty * 8 + i] = ix;
    }
    __syncthreads();

    // ---- gather: out[row] = E[best_idx[row]] (float4, coalesced) ----
    const float4* E4 = reinterpret_cast<const float4*>(E);
    float4*       O4 = reinterpret_cast<float4*>(out);
    int col = tid & 63;                      // 64 float4 per row
#pragma unroll
    for (int r = tid >> 6; r < BM; r += 4) {
        int idx = sIdx[r];
        O4[(size_t)(row0 + r) * (D / 4) + col] = E4[(size_t)idx * (D / 4) + col];
    }
}

extern "C" void kernel_launch(void* const* d_in, const int* in_sizes, int n_in,
                              void* d_out, int out_size) {
    const float* x = (const float*)d_in[0];          // [16,1024,256] f32
    const float* E = (const float*)d_in[1];          // [1024,256]    f32
    float* out = (float*)d_out;

    int rows = in_sizes[0] / D;                      // 16384

    e_half_kernel<<<(NCODES + 255) / 256, 256>>>(E);

    cudaFuncSetAttribute(vq_kernel, cudaFuncAttributeMaxDynamicSharedMemorySize, SMEM_BYTES);
    dim3 blk(32, 8);
    vq_kernel<<<rows / BM, blk, SMEM_BYTES>>>(x, E, out);
}

// round 4
// speedup vs baseline: 1.9169x; 1.9169x over previous
#include <cuda_runtime.h>
#include <cstdint>

#define D          256
#define NCODES     1024
#define ROWS_TOTAL 16384
#define BM         128
#define BN         256
#define KC         32
#define NKCH       24        // 3 segments * 8 chunks
#define NITER      4         // NCODES / BN

#define ASTRIDE_B   160      // bytes per smem row (40 words, 16B aligned)
#define A_STAGE     (BM * ASTRIDE_B)              // 20480
#define B_STAGE     (BN * ASTRIDE_B)              // 40960
#define STAGE_BYTES (A_STAGE + B_STAGE)           // 61440
#define B_OFF       A_STAGE
#define EHALF_OFF   (2 * STAGE_BYTES)             // 122880
#define RED_B_OFF   (EHALF_OFF + NCODES * 4)      // 126976
#define RED_I_OFF   (RED_B_OFF + 4 * 128 * 4)     // 129024
#define SMEM_TOTAL  (RED_I_OFF + 4 * 128 * 4)     // 131072

// split operands, k-interleaved: [seg hi | seg lo], 512 cols per row
__device__ float g_Xc[(size_t)ROWS_TOTAL * 512];   // 32 MB scratch
__device__ float g_Ec[(size_t)NCODES * 512];       // 2 MB
__device__ float g_e_half[NCODES];

// interleave k within its 8-group: pairs (k, k+4) adjacent -> LDS.64 fragments
__device__ __forceinline__ int ilv(int k) {
    return (k >> 3) * 8 + 2 * (k & 3) + ((k & 4) >> 2);
}
__device__ __forceinline__ float tf32_rn(float v) {
    uint32_t u;
    asm("cvt.rna.tf32.f32 %0, %1;" : "=r"(u) : "f"(v));
    return __uint_as_float(u);
}

__global__ void prep_x(const float* __restrict__ X) {
    for (int idx = blockIdx.x * blockDim.x + threadIdx.x;
         idx < ROWS_TOTAL * D; idx += gridDim.x * blockDim.x) {
        int m = idx >> 8, k = idx & 255;
        float v  = X[idx];
        float hi = tf32_rn(v);
        float lo = v - hi;                      // exact
        size_t base = (size_t)m * 512 + ilv(k);
        g_Xc[base]       = hi;
        g_Xc[base + 256] = lo;
    }
}

__global__ void prep_e(const float* __restrict__ E) {
    for (int idx = blockIdx.x * blockDim.x + threadIdx.x;
         idx < NCODES * D; idx += gridDim.x * blockDim.x) {
        int n = idx >> 8, k = idx & 255;
        float v  = E[idx];
        float hi = tf32_rn(v);
        float lo = v - hi;
        size_t base = (size_t)n * 512 + ilv(k);
        g_Ec[base]       = hi;
        g_Ec[base + 256] = lo;
    }
}

__global__ void e_half_kernel(const float* __restrict__ E) {
    int n = blockIdx.x * blockDim.x + threadIdx.x;
    if (n >= NCODES) return;
    const float4* row = reinterpret_cast<const float4*>(E + (size_t)n * D);
    float s = 0.f;
#pragma unroll
    for (int i = 0; i < D / 4; i++) {
        float4 v = row[i];
        s += v.x * v.x + v.y * v.y + v.z * v.z + v.w * v.w;
    }
    g_e_half[n] = 0.5f * s;
}

static __device__ __forceinline__ uint32_t smem_u32(const void* p) {
    uint32_t a;
    asm("{ .reg .u64 t; cvta.to.shared.u64 t, %1; cvt.u32.u64 %0, t; }" : "=r"(a) : "l"(p));
    return a;
}
#define CP16(dst, src) asm volatile("cp.async.cg.shared.global [%0], [%1], 16;" :: "r"(dst), "l"(src) : "memory")
#define LDS64(r0, r1, a) asm volatile("ld.shared.v2.b32 {%0,%1}, [%2];" : "=r"(r0), "=r"(r1) : "r"(a))
#define MMA_TF32(c, a, b) \
    asm volatile("mma.sync.aligned.m16n8k8.row.col.f32.tf32.tf32.f32 " \
                 "{%0,%1,%2,%3}, {%4,%5,%6,%7}, {%8,%9}, {%0,%1,%2,%3};" \
                 : "+f"((c)[0]), "+f"((c)[1]), "+f"((c)[2]), "+f"((c)[3]) \
                 : "r"((a)[0]), "r"((a)[1]), "r"((a)[2]), "r"((a)[3]), "r"((b)[0]), "r"((b)[1]))

__global__ __launch_bounds__(256, 1)
void vq_mma(const float* __restrict__ E, float* __restrict__ out) {
    extern __shared__ char smem[];
    const uint32_t sb = smem_u32(smem);
    float* ehs   = (float*)(smem + EHALF_OFF);
    float* sBest = (float*)(smem + RED_B_OFF);
    int*   sIdx  = (int*)(smem + RED_I_OFF);

    const int tid  = threadIdx.x;
    const int lane = tid & 31, wid = tid >> 5;
    const int wm = wid & 1, wn = wid >> 1;         // warp grid 2(M) x 4(N)
    const int g = lane >> 2, t = lane & 3;
    const int row0 = blockIdx.x * BM;

    for (int i = tid; i < NCODES; i += 256) ehs[i] = g_e_half[i];

    // ---- cp.async unit bases (row = (tid>>3) + 32*i, j = tid&7 for all units) ----
    const int urow = tid >> 3, uj = tid & 7;
    const float* aSrc0 = g_Xc + (size_t)(row0 + urow) * 512 + uj * 4;
    const uint32_t aDst0 = sb + urow * ASTRIDE_B + uj * 16;
    const uint32_t bDst0 = sb + B_OFF + urow * ASTRIDE_B + uj * 16;

    float best[8];
    int   bidx[8];
#pragma unroll
    for (int i = 0; i < 8; i++) { best[i] = -3.4e38f; bidx[i] = 0; }

    // LDS base addresses — FIX: include sb (dynamic smem base) in shared-window address
    const uint32_t aLds0 = sb + (uint32_t)((wm * 64 + g) * ASTRIDE_B + t * 8);
    const uint32_t bLds0 = sb + (uint32_t)(B_OFF + (wn * 64 + g) * ASTRIDE_B + t * 8);

    for (int ni = 0; ni < NITER; ni++) {
        const int n0 = ni * BN;
        const float* bSrc0 = g_Ec + (size_t)(n0 + urow) * 512 + uj * 4;

        float acc[4][8][4];
#pragma unroll
        for (int mi = 0; mi < 4; mi++)
#pragma unroll
            for (int nj = 0; nj < 8; nj++)
#pragma unroll
                for (int q = 0; q < 4; q++) acc[mi][nj][q] = 0.f;

        // prologue: chunk 0 -> stage 0 (seg 0 hi/hi)
        {
#pragma unroll
            for (int i = 0; i < 4; i++) CP16(aDst0 + i * (32 * ASTRIDE_B), aSrc0 + i * 16384);
#pragma unroll
            for (int i = 0; i < 8; i++) CP16(bDst0 + i * (32 * ASTRIDE_B), bSrc0 + i * 16384);
            asm volatile("cp.async.commit_group;" ::: "memory");
        }

        for (int kc = 0; kc < NKCH; kc++) {
            const uint32_t st = (uint32_t)(kc & 1) * STAGE_BYTES;

            if (kc + 1 < NKCH) {
                const int kn   = kc + 1;
                const int seg  = kn >> 3;
                const int aoff = ((seg == 2) ? 256 : 0) + (kn & 7) * 32;
                const int boff = ((seg == 1) ? 256 : 0) + (kn & 7) * 32;
                const uint32_t nst = (uint32_t)(kn & 1) * STAGE_BYTES;
#pragma unroll
                for (int i = 0; i < 4; i++)
                    CP16(nst + aDst0 + i * (32 * ASTRIDE_B), aSrc0 + aoff + i * 16384);
#pragma unroll
                for (int i = 0; i < 8; i++)
                    CP16(nst + bDst0 + i * (32 * ASTRIDE_B), bSrc0 + boff + i * 16384);
                asm volatile("cp.async.commit_group;" ::: "memory");
                asm volatile("cp.async.wait_group 1;" ::: "memory");
            } else {
                asm volatile("cp.async.wait_group 0;" ::: "memory");
            }
            __syncthreads();

#pragma unroll
            for (int s = 0; s < 4; s++) {            // 4 k-steps of 8
                uint32_t a[4][4];
#pragma unroll
                for (int mi = 0; mi < 4; mi++) {
                    uint32_t ad = st + aLds0 + (uint32_t)(mi * 16 * ASTRIDE_B + s * 32);
                    LDS64(a[mi][0], a[mi][2], ad);                       // row g:   k t, t+4
                    LDS64(a[mi][1], a[mi][3], ad + 8 * ASTRIDE_B);       // row g+8
                }
                uint32_t b[8][2];
#pragma unroll
                for (int nj = 0; nj < 8; nj++) {
                    uint32_t bd = st + bLds0 + (uint32_t)(nj * 8 * ASTRIDE_B + s * 32);
                    LDS64(b[nj][0], b[nj][1], bd);                       // code g: k t, t+4
                }
#pragma unroll
                for (int mi = 0; mi < 4; mi++)
#pragma unroll
                    for (int nj = 0; nj < 8; nj++)
                        MMA_TF32(acc[mi][nj], a[mi], b[nj]);
            }
            __syncthreads();
        }

        // ---- epilogue: scores = acc - 0.5||e||^2, update per-row best ----
#pragma unroll
        for (int mi = 0; mi < 4; mi++)
#pragma unroll
            for (int nj = 0; nj < 8; nj++)
#pragma unroll
                for (int q = 0; q < 4; q++) {
                    int slot = mi * 2 + (q >> 1);
                    int n = n0 + wn * 64 + nj * 8 + 2 * t + (q & 1);
                    float sc = acc[mi][nj][q] - ehs[n];
                    if (sc > best[slot]) { best[slot] = sc; bidx[slot] = n; }
                }
    }

    // ---- reduce across the 4 lanes (t) sharing each row ----
#pragma unroll
    for (int slot = 0; slot < 8; slot++) {
#pragma unroll
        for (int off = 1; off <= 2; off <<= 1) {
            float ob = __shfl_xor_sync(0xffffffffu, best[slot], off);
            int   oi = __shfl_xor_sync(0xffffffffu, bidx[slot], off);
            if (ob > best[slot] || (ob == best[slot] && oi < bidx[slot])) {
                best[slot] = ob; bidx[slot] = oi;
            }
        }
    }
    if (t == 0) {
#pragma unroll
        for (int slot = 0; slot < 8; slot++) {
            int mi = slot >> 1, qh = slot & 1;
            int row = wm * 64 + mi * 16 + g + 8 * qh;
            sBest[wn * 128 + row] = best[slot];
            sIdx[wn * 128 + row]  = bidx[slot];
        }
    }
    __syncthreads();

    // ---- reduce across the 4 N-warps, then gather ----
    if (tid < 128) {
        float bb = sBest[tid]; int bi = sIdx[tid];
#pragma unroll
        for (int w = 1; w < 4; w++) {
            float b2 = sBest[w * 128 + tid];
            int   i2 = sIdx[w * 128 + tid];
            if (b2 > bb || (b2 == bb && i2 < bi)) { bb = b2; bi = i2; }
        }
        sIdx[tid] = bi;
    }
    __syncthreads();

    const float4* E4 = reinterpret_cast<const float4*>(E);
    float4*       O4 = reinterpret_cast<float4*>(out);
    const int col = tid & 63;
#pragma unroll
    for (int r = tid >> 6; r < BM; r += 4) {
        int idx = sIdx[r];
        O4[(size_t)(row0 + r) * (D / 4) + col] = E4[(size_t)idx * (D / 4) + col];
    }
}

extern "C" void kernel_launch(void* const* d_in, const int* in_sizes, int n_in,
                              void* d_out, int out_size) {
    const float* x = (const float*)d_in[0];     // [16,1024,256] f32
    const float* E = (const float*)d_in[1];     // [1024,256]    f32
    float* out = (float*)d_out;

    e_half_kernel<<<(NCODES + 255) / 256, 256>>>(E);
    prep_e<<<256, 256>>>(E);
    prep_x<<<2048, 256>>>(x);

    cudaFuncSetAttribute(vq_mma, cudaFuncAttributeMaxDynamicSharedMemorySize, SMEM_TOTAL);
    vq_mma<<<ROWS_TOTAL / BM, 256, SMEM_TOTAL>>>(E, out);
}

// round 5
// speedup vs baseline: 3.3114x; 1.7275x over previous
#include <cuda_runtime.h>
#include <cuda_fp16.h>
#include <cstdint>

#define D          256
#define NCODES     1024
#define ROWS_TOTAL 16384
#define BM         128
#define BN         256
#define NKCH       12        // 3 segments * 4 chunks of 64 k
#define NITER      4         // NCODES / BN

#define ASTRIDE_B   160      // smem bytes per row (128 data + 32 pad), conflict-free
#define A_STAGE     (BM * ASTRIDE_B)              // 20480
#define B_STAGE     (BN * ASTRIDE_B)              // 40960
#define STAGE_BYTES (A_STAGE + B_STAGE)           // 61440
#define B_OFF       A_STAGE
#define EHALF_OFF   (2 * STAGE_BYTES)             // 122880
#define RED_B_OFF   (EHALF_OFF + NCODES * 4)      // 126976
#define RED_I_OFF   (RED_B_OFF + 4 * 128 * 4)     // 129024
#define SMEM_TOTAL  (RED_I_OFF + 4 * 128 * 4)     // 131072

// split operands as fp16, k-interleaved in 16-groups: [hi(256) | lo(256)] per row
__device__ __half g_Xc[(size_t)ROWS_TOTAL * 512];   // 16 MB
__device__ __half g_Ec[(size_t)NCODES * 512];       // 1 MB
__device__ float  g_e_half[NCODES];

// position of k (0..15) inside its 32-byte group so that lane t's LDS.64 at
// offset t*8 yields {2t,2t+1 | 2t+8,2t+9} — the m16n8k16 fragment pairs.
__device__ __forceinline__ int ilv16(int k) {
    return 4 * ((k & 7) >> 1) + 2 * (k >> 3) + (k & 1);
}

__global__ void prep_x(const float* __restrict__ X) {
    for (int idx = blockIdx.x * blockDim.x + threadIdx.x;
         idx < ROWS_TOTAL * D; idx += gridDim.x * blockDim.x) {
        int m = idx >> 8, k = idx & 255;
        float v = X[idx];
        __half hi = __float2half_rn(v);
        __half lo = __float2half_rn(v - __half2float(hi));
        size_t base = (size_t)m * 512 + (k >> 4) * 16 + ilv16(k & 15);
        g_Xc[base]       = hi;
        g_Xc[base + 256] = lo;
    }
}

__global__ void prep_e(const float* __restrict__ E) {
    for (int idx = blockIdx.x * blockDim.x + threadIdx.x;
         idx < NCODES * D; idx += gridDim.x * blockDim.x) {
        int n = idx >> 8, k = idx & 255;
        float v = E[idx];
        __half hi = __float2half_rn(v);
        __half lo = __float2half_rn(v - __half2float(hi));
        size_t base = (size_t)n * 512 + (k >> 4) * 16 + ilv16(k & 15);
        g_Ec[base]       = hi;
        g_Ec[base + 256] = lo;
    }
}

__global__ void e_half_kernel(const float* __restrict__ E) {
    int n = blockIdx.x * blockDim.x + threadIdx.x;
    if (n >= NCODES) return;
    const float4* row = reinterpret_cast<const float4*>(E + (size_t)n * D);
    float s = 0.f;
#pragma unroll
    for (int i = 0; i < D / 4; i++) {
        float4 v = row[i];
        s += v.x * v.x + v.y * v.y + v.z * v.z + v.w * v.w;
    }
    g_e_half[n] = 0.5f * s;
}

static __device__ __forceinline__ uint32_t smem_u32(const void* p) {
    uint32_t a;
    asm("{ .reg .u64 t; cvta.to.shared.u64 t, %1; cvt.u32.u64 %0, t; }" : "=r"(a) : "l"(p));
    return a;
}
#define CP16(dst, src) asm volatile("cp.async.cg.shared.global [%0], [%1], 16;" :: "r"(dst), "l"(src) : "memory")
#define LDS64(r0, r1, a) asm volatile("ld.shared.v2.b32 {%0,%1}, [%2];" : "=r"(r0), "=r"(r1) : "r"(a))
#define MMA_F16(c, a, b) \
    asm volatile("mma.sync.aligned.m16n8k16.row.col.f32.f16.f16.f32 " \
                 "{%0,%1,%2,%3}, {%4,%5,%6,%7}, {%8,%9}, {%0,%1,%2,%3};" \
                 : "+f"((c)[0]), "+f"((c)[1]), "+f"((c)[2]), "+f"((c)[3]) \
                 : "r"((a)[0]), "r"((a)[1]), "r"((a)[2]), "r"((a)[3]), "r"((b)[0]), "r"((b)[1]))

__global__ __launch_bounds__(256, 1)
void vq_mma(const float* __restrict__ E, float* __restrict__ out) {
    extern __shared__ char smem[];
    const uint32_t sb = smem_u32(smem);
    float* ehs   = (float*)(smem + EHALF_OFF);
    float* sBest = (float*)(smem + RED_B_OFF);
    int*   sIdx  = (int*)(smem + RED_I_OFF);

    const int tid  = threadIdx.x;
    const int lane = tid & 31, wid = tid >> 5;
    const int wm = wid & 1, wn = wid >> 1;         // warp grid 2(M) x 4(N)
    const int g = lane >> 2, t = lane & 3;
    const int row0 = blockIdx.x * BM;

    for (int i = tid; i < NCODES; i += 256) ehs[i] = g_e_half[i];

    // ---- cp.async 16B-unit assignments: row = tid>>3 (+32i), j = tid&7 ----
    const int urow = tid >> 3, uj = tid & 7;
    const char* aSrc0 = (const char*)(g_Xc + (size_t)(row0 + urow) * 512) + uj * 16;
    const uint32_t aDst0 = sb + urow * ASTRIDE_B + uj * 16;
    const uint32_t bDst0 = sb + B_OFF + urow * ASTRIDE_B + uj * 16;

    float best[8];
    int   bidx[8];
#pragma unroll
    for (int i = 0; i < 8; i++) { best[i] = -3.4e38f; bidx[i] = 0; }

    const uint32_t aLds0 = sb + (uint32_t)((wm * 64 + g) * ASTRIDE_B + t * 8);
    const uint32_t bLds0 = sb + (uint32_t)(B_OFF + (wn * 64 + g) * ASTRIDE_B + t * 8);

    for (int ni = 0; ni < NITER; ni++) {
        const int n0 = ni * BN;
        const char* bSrc0 = (const char*)(g_Ec + (size_t)(n0 + urow) * 512) + uj * 16;

        float acc[4][8][4];
#pragma unroll
        for (int mi = 0; mi < 4; mi++)
#pragma unroll
            for (int nj = 0; nj < 8; nj++)
#pragma unroll
                for (int q = 0; q < 4; q++) acc[mi][nj][q] = 0.f;

        // prologue: chunk 0 -> stage 0 (hi/hi, k 0..63)
        {
#pragma unroll
            for (int i = 0; i < 4; i++) CP16(aDst0 + i * (32 * ASTRIDE_B), aSrc0 + i * 32 * 1024);
#pragma unroll
            for (int i = 0; i < 8; i++) CP16(bDst0 + i * (32 * ASTRIDE_B), bSrc0 + i * 32 * 1024);
            asm volatile("cp.async.commit_group;" ::: "memory");
        }

        for (int kc = 0; kc < NKCH; kc++) {
            const uint32_t st = (uint32_t)(kc & 1) * STAGE_BYTES;

            if (kc + 1 < NKCH) {
                const int kn = kc + 1;
                // A segs {hi,hi,lo}; B segs {hi,lo,hi}; each chunk = 128 bytes of a segment
                const int aoffB = (((kn >> 2) == 2) ? 512 : 0) + (kn & 3) * 128;
                const int boffB = (((kn >> 2) == 1) ? 512 : 0) + (kn & 3) * 128;
                const uint32_t nst = (uint32_t)(kn & 1) * STAGE_BYTES;
#pragma unroll
                for (int i = 0; i < 4; i++)
                    CP16(nst + aDst0 + i * (32 * ASTRIDE_B), aSrc0 + aoffB + i * 32 * 1024);
#pragma unroll
                for (int i = 0; i < 8; i++)
                    CP16(nst + bDst0 + i * (32 * ASTRIDE_B), bSrc0 + boffB + i * 32 * 1024);
                asm volatile("cp.async.commit_group;" ::: "memory");
                asm volatile("cp.async.wait_group 1;" ::: "memory");
            } else {
                asm volatile("cp.async.wait_group 0;" ::: "memory");
            }
            __syncthreads();

#pragma unroll
            for (int s = 0; s < 4; s++) {            // 4 k-steps of 16
                uint32_t a[4][4];
#pragma unroll
                for (int mi = 0; mi < 4; mi++) {
                    uint32_t ad = st + aLds0 + (uint32_t)(mi * 16 * ASTRIDE_B + s * 32);
                    LDS64(a[mi][0], a[mi][2], ad);                     // row g:   {2t,2t+1},{2t+8,2t+9}
                    LDS64(a[mi][1], a[mi][3], ad + 8 * ASTRIDE_B);     // row g+8
                }
                uint32_t b[8][2];
#pragma unroll
                for (int nj = 0; nj < 8; nj++) {
                    uint32_t bd = st + bLds0 + (uint32_t)(nj * 8 * ASTRIDE_B + s * 32);
                    LDS64(b[nj][0], b[nj][1], bd);                     // code g: b0, b1
                }
#pragma unroll
                for (int mi = 0; mi < 4; mi++)
#pragma unroll
                    for (int nj = 0; nj < 8; nj++)
                        MMA_F16(acc[mi][nj], a[mi], b[nj]);
            }
            __syncthreads();
        }

        // ---- epilogue: score = acc - 0.5||e||^2, update per-row best ----
#pragma unroll
        for (int mi = 0; mi < 4; mi++)
#pragma unroll
            for (int nj = 0; nj < 8; nj++)
#pragma unroll
                for (int q = 0; q < 4; q++) {
                    int slot = mi * 2 + (q >> 1);
                    int n = n0 + wn * 64 + nj * 8 + 2 * t + (q & 1);
                    float sc = acc[mi][nj][q] - ehs[n];
                    if (sc > best[slot]) { best[slot] = sc; bidx[slot] = n; }
                }
    }

    // ---- reduce across the 4 lanes (t) sharing each row ----
#pragma unroll
    for (int slot = 0; slot < 8; slot++) {
#pragma unroll
        for (int off = 1; off <= 2; off <<= 1) {
            float ob = __shfl_xor_sync(0xffffffffu, best[slot], off);
            int   oi = __shfl_xor_sync(0xffffffffu, bidx[slot], off);
            if (ob > best[slot] || (ob == best[slot] && oi < bidx[slot])) {
                best[slot] = ob; bidx[slot] = oi;
            }
        }
    }
    if (t == 0) {
#pragma unroll
        for (int slot = 0; slot < 8; slot++) {
            int mi = slot >> 1, qh = slot & 1;
            int row = wm * 64 + mi * 16 + g + 8 * qh;
            sBest[wn * 128 + row] = best[slot];
            sIdx[wn * 128 + row]  = bidx[slot];
        }
    }
    __syncthreads();

    // ---- reduce across the 4 N-warps, then gather ----
    if (tid < 128) {
        float bb = sBest[tid]; int bi = sIdx[tid];
#pragma unroll
        for (int w = 1; w < 4; w++) {
            float b2 = sBest[w * 128 + tid];
            int   i2 = sIdx[w * 128 + tid];
            if (b2 > bb || (b2 == bb && i2 < bi)) { bb = b2; bi = i2; }
        }
        sIdx[tid] = bi;
    }
    __syncthreads();

    const float4* E4 = reinterpret_cast<const float4*>(E);
    float4*       O4 = reinterpret_cast<float4*>(out);
    const int col = tid & 63;
#pragma unroll
    for (int r = tid >> 6; r < BM; r += 4) {
        int idx = sIdx[r];
        O4[(size_t)(row0 + r) * (D / 4) + col] = E4[(size_t)idx * (D / 4) + col];
    }
}

extern "C" void kernel_launch(void* const* d_in, const int* in_sizes, int n_in,
                              void* d_out, int out_size) {
    const float* x = (const float*)d_in[0];     // [16,1024,256] f32
    const float* E = (const float*)d_in[1];     // [1024,256]    f32
    float* out = (float*)d_out;

    e_half_kernel<<<(NCODES + 255) / 256, 256>>>(E);
    prep_e<<<256, 256>>>(E);
    prep_x<<<2048, 256>>>(x);

    cudaFuncSetAttribute(vq_mma, cudaFuncAttributeMaxDynamicSharedMemorySize, SMEM_TOTAL);
    vq_mma<<<ROWS_TOTAL / BM, 256, SMEM_TOTAL>>>(E, out);
}